// round 13
// baseline (speedup 1.0000x reference)
#include <cuda_runtime.h>
#include <cuda_bf16.h>
#include <cuda_fp16.h>
#include <math.h>
#include <stdint.h>

// Problem dims
#define E_  768
#define H_  12
#define D_  64
#define B_  8
#define LO_ 512
#define LV_ 1024
#define LL_ 1024
#define LS_ 2048
#define Z_  (B_ * H_)     // 96
#define E2_ 1536

#define PADC 72                          // padded row stride for 64-wide tiles
#define TILE64B (128 * PADC * 2)         // 18432 B: one 128x64 fp16 tile
#define STGP (2 * TILE64B)               // proj stage: A + B = 36864
#define SMEM_PROJ (3 * STGP)             // 110592
// attn v5: 2 stages x (K+V) + 2 Q tiles (64 rows) = 73728 + 18432 = 92160
#define STGF (2 * TILE64B)               // 36864
#define QTILE (64 * PADC * 2)            // 9216
#define SMEM_ATTN (2 * STGF + 2 * QTILE) // 92160 -> 2 CTAs/SM
#define QOFF (2 * STGF)
#define RS2 (2 * E_)

// ---------------------------------------------------------------------------
// Scratch
// ---------------------------------------------------------------------------
__device__ __half g_Oh [(size_t)B_ * LO_ * E_];
__device__ __half g_Vh [(size_t)B_ * LV_ * E_];
__device__ __half g_Lh [(size_t)B_ * LL_ * E_];
__device__ __half g_w1h[(size_t)(3 * E_) * E_];
__device__ __half g_w2h[(size_t)(3 * E_) * E_];
__device__ __half g_ctxh[(size_t)B_ * LO_ * RS2];   // fp16 hi/lo planes
__device__ __half g_owh [(size_t)E_ * E_];

__device__ __half g_qq [(size_t)B_ * LO_ * E2_];
__device__ __half g_kv1[(size_t)B_ * LV_ * E2_];
__device__ __half g_kv2[(size_t)B_ * LL_ * E2_];
__device__ __half g_Eh [(size_t)Z_ * LO_ * LS_];
__device__ float  g_inv[(size_t)Z_ * LO_];

// ---------------------------------------------------------------------------
// Helpers
// ---------------------------------------------------------------------------
__device__ __forceinline__ uint32_t smem_u32(const void* p) {
    uint32_t a;
    asm("{ .reg .u64 t; cvta.to.shared.u64 t, %1; cvt.u32.u64 %0, t; }"
        : "=r"(a) : "l"(p));
    return a;
}
__device__ __forceinline__ void cpa16(uint32_t s, const void* g) {
    asm volatile("cp.async.cg.shared.global [%0], [%1], 16;" :: "r"(s), "l"(g));
}
__device__ __forceinline__ void ldm_x4(uint32_t& r0, uint32_t& r1, uint32_t& r2,
                                       uint32_t& r3, uint32_t addr) {
    asm volatile("ldmatrix.sync.aligned.m8n8.x4.shared.b16 {%0,%1,%2,%3}, [%4];"
        : "=r"(r0), "=r"(r1), "=r"(r2), "=r"(r3) : "r"(addr));
}
__device__ __forceinline__ void ldm_x4_t(uint32_t& r0, uint32_t& r1, uint32_t& r2,
                                         uint32_t& r3, uint32_t addr) {
    asm volatile("ldmatrix.sync.aligned.m8n8.x4.trans.shared.b16 {%0,%1,%2,%3}, [%4];"
        : "=r"(r0), "=r"(r1), "=r"(r2), "=r"(r3) : "r"(addr));
}
__device__ __forceinline__ void mma_hf(float* d, const uint32_t* a,
                                       uint32_t b0, uint32_t b1) {
    asm volatile(
        "mma.sync.aligned.m16n8k16.row.col.f32.f16.f16.f32 "
        "{%0,%1,%2,%3}, {%4,%5,%6,%7}, {%8,%9}, {%0,%1,%2,%3};"
        : "+f"(d[0]), "+f"(d[1]), "+f"(d[2]), "+f"(d[3])
        : "r"(a[0]), "r"(a[1]), "r"(a[2]), "r"(a[3]), "r"(b0), "r"(b1));
}
__device__ __forceinline__ void fsplit_hf(float x, __half& h, __half& l) {
    h = __float2half_rn(x);
    l = __float2half_rn(x - __half2float(h));
}

// ---------------------------------------------------------------------------
// Fused split: V,L,O,w1,w2,ow -> fp16 single plane.
// ---------------------------------------------------------------------------
#define RV 8192
#define RL 16384
#define RO 20480
#define RW1 22784
#define RW2 25088
#define ROW 25856
__global__ __launch_bounds__(256) void split_all(
    const float* __restrict__ V, const float* __restrict__ L,
    const float* __restrict__ O, const float* __restrict__ w1,
    const float* __restrict__ w2, const float* __restrict__ ow,
    __half* __restrict__ Vh, __half* __restrict__ Lh,
    __half* __restrict__ Oh, __half* __restrict__ w1h,
    __half* __restrict__ w2h, __half* __restrict__ owh)
{
    const int CP = E_ / 4;
    int gid = blockIdx.x * 256 + threadIdx.x;
    int r = gid / CP, c4 = (gid % CP) * 4;
    const float* x;
    __half* y;
    if      (r < RV)  { x = V;  y = Vh;  }
    else if (r < RL)  { x = L;  y = Lh;  r -= RV; }
    else if (r < RO)  { x = O;  y = Oh;  r -= RL; }
    else if (r < RW1) { x = w1; y = w1h; r -= RO; }
    else if (r < RW2) { x = w2; y = w2h; r -= RW1; }
    else if (r < ROW) { x = ow; y = owh; r -= RW2; }
    else return;
    float4 v = *(const float4*)(x + (size_t)r * E_ + c4);
    float vv[4] = {v.x, v.y, v.z, v.w};
    uint64_t hp = 0;
    #pragma unroll
    for (int i = 0; i < 4; i++)
        hp |= (uint64_t)__half_as_ushort(__float2half_rn(vv[i])) << (16 * i);
    *(uint64_t*)(y + (size_t)r * E_ + c4) = hp;
}

// ---------------------------------------------------------------------------
// q/k/v projections (fp16 1-plane, K'=768): unchanged.
// ---------------------------------------------------------------------------
__global__ __launch_bounds__(256, 2) void proj_qkv(
    const __half* __restrict__ Oh, const __half* __restrict__ Vh,
    const __half* __restrict__ Lh,
    const __half* __restrict__ w1h, const __half* __restrict__ w2h,
    const float* __restrict__ b1, const float* __restrict__ b2,
    __half* __restrict__ qq, __half* __restrict__ kv1, __half* __restrict__ kv2)
{
    extern __shared__ char smx[];
    const uint32_t base = smem_u32(smx);
    const int z = blockIdx.z;
    const size_t WS = (size_t)E_ * E_;
    const __half *A, *W1, *W2;
    const float *bi1, *bi2;
    __half* out;
    if (z == 0) {
        if (blockIdx.y >= 32) return;
        A = Oh; W1 = w1h; W2 = w2h; bi1 = b1; bi2 = b2; out = qq;
    } else if (z == 1) {
        A = Vh; W1 = w1h + WS; W2 = w1h + 2 * WS;
        bi1 = b1 + E_; bi2 = b1 + 2 * E_; out = kv1;
    } else {
        A = Lh; W1 = w2h + WS; W2 = w2h + 2 * WS;
        bi1 = b2 + E_; bi2 = b2 + 2 * E_; out = kv2;
    }
    const int n0 = blockIdx.x * 128;
    const int m0 = blockIdx.y * 128;
    const __half* Wb = (n0 < E_) ? W1 + (size_t)n0 * E_
                                 : W2 + (size_t)(n0 - E_) * E_;
    const float* biasb = (n0 < E_) ? bi1 + n0 : bi2 + (n0 - E_);

    const int tid  = threadIdx.x;
    const int warp = tid >> 5, lane = tid & 31;
    const int wm = warp >> 2, wn = warp & 3;

    const int rA = tid >> 3;
    const int c8 = (tid & 7) * 8;
    const __half* aP = A + (size_t)(m0 + rA) * E_ + c8;
    const __half* wP = Wb + (size_t)rA * E_ + c8;
    const uint32_t off0 = 2u * (rA * PADC + c8);

    #define PLOADH(j) do { \
        int _ko = (j) * 64; \
        uint32_t _sb = base + ((j) % 3) * STGP; \
        _Pragma("unroll") \
        for (int _i = 0; _i < 4; _i++) { \
            cpa16(_sb + off0 + _i * (2 * 32 * PADC), aP + _ko + (size_t)_i * 32 * E_); \
            cpa16(_sb + TILE64B + off0 + _i * (2 * 32 * PADC), wP + _ko + (size_t)_i * 32 * E_); \
        } \
        asm volatile("cp.async.commit_group;" ::: "memory"); \
    } while (0)

    PLOADH(0); PLOADH(1);

    const int lr = lane & 15;
    const int lh = (lane >> 4) * 8;

    float acc[4][4][4];
    #pragma unroll
    for (int i = 0; i < 4; i++)
        #pragma unroll
        for (int j = 0; j < 4; j++)
            #pragma unroll
            for (int q = 0; q < 4; q++) acc[i][j][q] = 0.f;

    const int NCHUNK = 12;
    for (int c = 0; c < NCHUNK; c++) {
        asm volatile("cp.async.wait_group 1;" ::: "memory");
        __syncthreads();
        if (c + 2 < NCHUNK) PLOADH(c + 2);
        else asm volatile("cp.async.commit_group;" ::: "memory");

        const uint32_t ab = base + (c % 3) * STGP;
        const uint32_t bb = ab + TILE64B;
        #pragma unroll
        for (int kf = 0; kf < 4; kf++) {
            uint32_t a[4][4];
            #pragma unroll
            for (int mi = 0; mi < 4; mi++)
                ldm_x4(a[mi][0], a[mi][1], a[mi][2], a[mi][3],
                       ab + 2u * ((wm * 64 + mi * 16 + lr) * PADC + kf * 16 + lh));
            uint32_t br[2][4];
            #pragma unroll
            for (int g = 0; g < 2; g++)
                ldm_x4(br[g][0], br[g][1], br[g][2], br[g][3],
                       bb + 2u * ((wn * 32 + g * 16 + lr) * PADC + kf * 16 + lh));
            #pragma unroll
            for (int mi = 0; mi < 4; mi++)
                #pragma unroll
                for (int g = 0; g < 2; g++)
                    #pragma unroll
                    for (int s = 0; s < 2; s++)
                        mma_hf(acc[mi][g * 2 + s], a[mi], br[g][s], br[g][s + 2]);
        }
    }
    #undef PLOADH

    const int er = lane >> 2;
    const int ec = (lane & 3) * 2;
    #pragma unroll
    for (int mi = 0; mi < 4; mi++) {
        #pragma unroll
        for (int ni = 0; ni < 4; ni++) {
            int m = m0 + wm * 64 + mi * 16 + er;
            int cl = wn * 32 + ni * 8 + ec;
            float bx = __ldg(biasb + cl), by = __ldg(biasb + cl + 1);
            *(__half2*)(out + (size_t)m * E2_ + n0 + cl) =
                __floats2half2_rn(acc[mi][ni][0] + bx, acc[mi][ni][1] + by);
            *(__half2*)(out + (size_t)(m + 8) * E2_ + n0 + cl) =
                __floats2half2_rn(acc[mi][ni][2] + bx, acc[mi][ni][3] + by);
        }
    }
}

// ---------------------------------------------------------------------------
// Output projection (fp16 2-term, K'=1536): unchanged from R12.
// ---------------------------------------------------------------------------
__global__ __launch_bounds__(256, 2) void proj_out(
    const __half* __restrict__ A,
    const __half* __restrict__ W,
    const float* __restrict__ ob, float* __restrict__ out)
{
    extern __shared__ char smx[];
    const uint32_t base = smem_u32(smx);
    const int n0 = blockIdx.x * 128;
    const int m0 = blockIdx.y * 128;
    const __half* Wb = W + (size_t)n0 * E_;
    const float* biasb = ob + n0;

    const int tid  = threadIdx.x;
    const int warp = tid >> 5, lane = tid & 31;
    const int wm = warp >> 2, wn = warp & 3;

    const int rA = tid >> 3;
    const int c8 = (tid & 7) * 8;
    const __half* aP = A + (size_t)(m0 + rA) * RS2 + c8;
    const __half* wP = Wb + (size_t)rA * E_ + c8;
    const uint32_t off0 = 2u * (rA * PADC + c8);

    #define PLOAD(j) do { \
        int _t = (j) / 12, _ko = ((j) % 12) * 64; \
        int _ap = _t * E_; \
        uint32_t _sb = base + ((j) % 3) * STGP; \
        _Pragma("unroll") \
        for (int _i = 0; _i < 4; _i++) { \
            cpa16(_sb + off0 + _i * (2 * 32 * PADC), aP + _ap + _ko + (size_t)_i * 32 * RS2); \
            cpa16(_sb + TILE64B + off0 + _i * (2 * 32 * PADC), wP + _ko + (size_t)_i * 32 * E_); \
        } \
        asm volatile("cp.async.commit_group;" ::: "memory"); \
    } while (0)

    PLOAD(0); PLOAD(1);

    const int lr = lane & 15;
    const int lh = (lane >> 4) * 8;

    float acc[4][4][4];
    #pragma unroll
    for (int i = 0; i < 4; i++)
        #pragma unroll
        for (int j = 0; j < 4; j++)
            #pragma unroll
            for (int q = 0; q < 4; q++) acc[i][j][q] = 0.f;

    const int NCHUNK = 24;
    for (int c = 0; c < NCHUNK; c++) {
        asm volatile("cp.async.wait_group 1;" ::: "memory");
        __syncthreads();
        if (c + 2 < NCHUNK) PLOAD(c + 2);
        else asm volatile("cp.async.commit_group;" ::: "memory");

        const uint32_t ab = base + (c % 3) * STGP;
        const uint32_t bb = ab + TILE64B;
        #pragma unroll
        for (int kf = 0; kf < 4; kf++) {
            uint32_t a[4][4];
            #pragma unroll
            for (int mi = 0; mi < 4; mi++)
                ldm_x4(a[mi][0], a[mi][1], a[mi][2], a[mi][3],
                       ab + 2u * ((wm * 64 + mi * 16 + lr) * PADC + kf * 16 + lh));
            uint32_t br[2][4];
            #pragma unroll
            for (int g = 0; g < 2; g++)
                ldm_x4(br[g][0], br[g][1], br[g][2], br[g][3],
                       bb + 2u * ((wn * 32 + g * 16 + lr) * PADC + kf * 16 + lh));
            #pragma unroll
            for (int mi = 0; mi < 4; mi++)
                #pragma unroll
                for (int g = 0; g < 2; g++)
                    #pragma unroll
                    for (int s = 0; s < 2; s++)
                        mma_hf(acc[mi][g * 2 + s], a[mi], br[g][s], br[g][s + 2]);
        }
    }
    #undef PLOAD

    const int er = lane >> 2;
    const int ec = (lane & 3) * 2;
    #pragma unroll
    for (int mi = 0; mi < 4; mi++) {
        #pragma unroll
        for (int ni = 0; ni < 4; ni++) {
            int m = m0 + wm * 64 + mi * 16 + er;
            int cl = wn * 32 + ni * 8 + ec;
            float bx = __ldg(biasb + cl), by = __ldg(biasb + cl + 1);
            *(float2*)(out + (size_t)m * E_ + n0 + cl) =
                make_float2(acc[mi][ni][0] + bx, acc[mi][ni][1] + by);
            *(float2*)(out + (size_t)(m + 8) * E_ + n0 + cl) =
                make_float2(acc[mi][ni][2] + bx, acc[mi][ni][3] + by);
        }
    }
}

// ---------------------------------------------------------------------------
// Fused attention v5: m-tile 64, 512 threads, warps = 4(M,16 rows) x 4(s-
// quarter, 32 cols), 2-stage K/V, 2 CTAs/SM. grid (8, 96).
// ---------------------------------------------------------------------------
__global__ __launch_bounds__(512, 2) void attn_fused(
    const __half* __restrict__ Q, const __half* __restrict__ KV1,
    const __half* __restrict__ KV2,
    const float* __restrict__ mask,
    __half* __restrict__ Eo, float* __restrict__ Inv,
    __half* __restrict__ Cs)
{
    extern __shared__ char smx[];
    const uint32_t base = smem_u32(smx);

    const int tid  = threadIdx.x;
    const int warp = tid >> 5, lane = tid & 31;
    const int mw = warp & 3;          // m-tile (16 rows)
    const int sq = warp >> 2;         // s-quarter (32 cols)
    const int z = blockIdx.y;
    const int b = z / H_, h = z % H_;
    const int m0 = blockIdx.x * 64;

    int rk[2];
    const int ckc = (tid & 7) * 8;
    rk[0] = tid >> 3;
    rk[1] = (tid + 512) >> 3;

    // Q tiles: 2 x 64 rows x 8 chunks = 1024 chunks, 2/thread (group 0).
    #pragma unroll
    for (int i = 0; i < 2; i++) {
        int idx = tid + i * 512;
        int tile = idx >> 9;
        int w = idx & 511;
        int r = w >> 3, c = (w & 7) * 8;
        cpa16(base + QOFF + tile * QTILE + 2u * (r * PADC + c),
              Q + (size_t)(b * LO_ + m0 + r) * E2_ + tile * E_ + h * D_ + c);
    }

    #define AKV(j) do { \
        const __half* _kb = ((j) < 8) ? KV1 : KV2; \
        int _s0 = (((j) < 8) ? (j) : ((j) - 8)) * 128; \
        uint32_t _sb = base + ((j) & 1) * STGF; \
        _Pragma("unroll") \
        for (int _i = 0; _i < 2; _i++) { \
            const __half* _row = _kb + (size_t)(b * LV_ + _s0 + rk[_i]) * E2_ + h * D_ + ckc; \
            uint32_t _o = 2u * (rk[_i] * PADC + ckc); \
            cpa16(_sb + _o, _row); \
            cpa16(_sb + TILE64B + _o, _row + E_); \
        } \
        asm volatile("cp.async.commit_group;" ::: "memory"); \
    } while (0)

    AKV(0);
    AKV(1);

    const int lr = lane & 15;
    const int lh = (lane >> 4) * 8;
    const int er = lane >> 2;
    const int ec = (lane & 3) * 2;
    const int tg  = lane >> 3;
    const int tlr = lane & 7;
    const int tko = (tg & 1) * 8;
    const int tno = (tg >> 1) * 8;

    const int row0 = m0 + mw * 16 + er;
    const int row1 = row0 + 8;

    float acc_c[8][4];
    #pragma unroll
    for (int j = 0; j < 8; j++)
        #pragma unroll
        for (int q = 0; q < 4; q++) acc_c[j][q] = 0.f;

    uint32_t qf[4][4];
    float rs0 = 0.f, rs1 = 0.f;

    for (int nt = 0; nt < 16; nt++) {
        asm volatile("cp.async.wait_group 1;" ::: "memory");
        __syncthreads();

        if (nt == 0 || nt == 8) {
            uint32_t qb = base + QOFF + (nt == 8 ? QTILE : 0);
            #pragma unroll
            for (int kf = 0; kf < 4; kf++)
                ldm_x4(qf[kf][0], qf[kf][1], qf[kf][2], qf[kf][3],
                       qb + 2u * ((mw * 16 + lr) * PADC + kf * 16 + lh));
        }

        const uint32_t kb = base + (nt & 1) * STGF;
        const uint32_t vb = kb + TILE64B;

        // ---- scores: S[16 x 32] on this warp's s-quarter ----
        float acc_s[4][4];
        #pragma unroll
        for (int j = 0; j < 4; j++)
            #pragma unroll
            for (int q = 0; q < 4; q++) acc_s[j][q] = 0.f;

        #pragma unroll
        for (int kf = 0; kf < 4; kf++) {
            #pragma unroll
            for (int g = 0; g < 2; g++) {
                uint32_t br[4];
                ldm_x4(br[0], br[1], br[2], br[3],
                       kb + 2u * ((sq * 32 + g * 16 + lr) * PADC + kf * 16 + lh));
                mma_hf(acc_s[2 * g],     qf[kf], br[0], br[2]);
                mma_hf(acc_s[2 * g + 1], qf[kf], br[1], br[3]);
            }
        }

        // ---- mask + exp + E store + rowsum + P fragments ----
        const int nbase = nt * 128 + sq * 32;
        uint32_t ph[4][2];
        #pragma unroll
        for (int j = 0; j < 4; j++) {
            int n = nbase + j * 8 + ec;
            float2 mk0 = *(const float2*)(mask + (size_t)row0 * LS_ + n);
            float2 mk1 = *(const float2*)(mask + (size_t)row1 * LS_ + n);
            float e0 = __expf(fminf(acc_s[j][0] * 0.125f + mk0.x, 11.f));
            float e1 = __expf(fminf(acc_s[j][1] * 0.125f + mk0.y, 11.f));
            float e2 = __expf(fminf(acc_s[j][2] * 0.125f + mk1.x, 11.f));
            float e3 = __expf(fminf(acc_s[j][3] * 0.125f + mk1.y, 11.f));
            __half2 u01 = __floats2half2_rn(e0, e1);
            __half2 u23 = __floats2half2_rn(e2, e3);
            ph[j][0] = *(uint32_t*)&u01;
            ph[j][1] = *(uint32_t*)&u23;
            *(__half2*)(Eo + ((size_t)z * LO_ + row0) * LS_ + n) = u01;
            *(__half2*)(Eo + ((size_t)z * LO_ + row1) * LS_ + n) = u23;
            rs0 += e0 + e1;
            rs1 += e2 + e3;
        }

        // ---- ctx partial: acc_c += P[16 x 32] @ V[32 x 64] ----
        #pragma unroll
        for (int kt = 0; kt < 2; kt++) {
            uint32_t pa[4] = {ph[2 * kt][0], ph[2 * kt][1],
                              ph[2 * kt + 1][0], ph[2 * kt + 1][1]};
            #pragma unroll
            for (int g = 0; g < 4; g++) {
                uint32_t rb[4];
                ldm_x4_t(rb[0], rb[1], rb[2], rb[3],
                         vb + 2u * ((sq * 32 + kt * 16 + tko + tlr) * PADC + g * 16 + tno));
                mma_hf(acc_c[2 * g],     pa, rb[0], rb[1]);
                mma_hf(acc_c[2 * g + 1], pa, rb[2], rb[3]);
            }
        }

        __syncthreads();   // readers of stage (nt&1) done before refill
        if (nt + 2 < 16) AKV(nt + 2);
        else asm volatile("cp.async.commit_group;" ::: "memory");
    }
    #undef AKV

    // ---- cross-warp combine (4 s-quarters) ----
    rs0 += __shfl_xor_sync(~0u, rs0, 1);
    rs0 += __shfl_xor_sync(~0u, rs0, 2);
    rs1 += __shfl_xor_sync(~0u, rs1, 1);
    rs1 += __shfl_xor_sync(~0u, rs1, 2);

    __syncthreads();   // all smem reads done before aliasing buffers

    // srs: [16 warps][8 rows][2] floats = 1KB at smx.
    float* srs = (float*)smx;
    if ((lane & 3) == 0) {
        srs[(warp * 8 + er) * 2 + 0] = rs0;
        srs[(warp * 8 + er) * 2 + 1] = rs1;
    }
    // panes: warps with sq>=1 dump acc_c. pane index = mw*3 + (sq-1); 4KB each.
    if (sq >= 1) {
        float* pane = (float*)(smx + 1024) + (mw * 3 + (sq - 1)) * 1024;
        #pragma unroll
        for (int j = 0; j < 8; j++)
            #pragma unroll
            for (int q = 0; q < 4; q++)
                pane[(j * 4 + q) * 32 + lane] = acc_c[j][q];
    }
    __syncthreads();

    if (sq == 0) {
        float t0 = rs0, t1 = rs1;
        #pragma unroll
        for (int s = 1; s < 4; s++) {
            t0 += srs[((s * 4 + mw) * 8 + er) * 2 + 0];
            t1 += srs[((s * 4 + mw) * 8 + er) * 2 + 1];
        }
        float inv0 = 1.f / t0;
        float inv1 = 1.f / t1;
        if ((lane & 3) == 0) {
            Inv[(size_t)z * LO_ + row0] = inv0;
            Inv[(size_t)z * LO_ + row1] = inv1;
        }
        #pragma unroll
        for (int s = 0; s < 3; s++) {
            const float* pane = (const float*)(smx + 1024) + (mw * 3 + s) * 1024;
            #pragma unroll
            for (int j = 0; j < 8; j++)
                #pragma unroll
                for (int q = 0; q < 4; q++)
                    acc_c[j][q] += pane[(j * 4 + q) * 32 + lane];
        }

        #pragma unroll
        for (int j = 0; j < 8; j++) {
            int nl = j * 8 + ec;
            __half* d0 = Cs + (size_t)(b * LO_ + row0) * RS2 + h * D_ + nl;
            __half* d1 = Cs + (size_t)(b * LO_ + row1) * RS2 + h * D_ + nl;
            __half h0, l0, h1, l1;
            fsplit_hf(acc_c[j][0] * inv0, h0, l0);
            fsplit_hf(acc_c[j][1] * inv0, h1, l1);
            *(__half2*)(d0)      = __half2(h0, h1);
            *(__half2*)(d0 + E_) = __half2(l0, l1);
            fsplit_hf(acc_c[j][2] * inv1, h0, l0);
            fsplit_hf(acc_c[j][3] * inv1, h1, l1);
            *(__half2*)(d1)      = __half2(h0, h1);
            *(__half2*)(d1 + E_) = __half2(l0, l1);
        }
    }
}

// ---------------------------------------------------------------------------
// Head-average: pure stream.
// ---------------------------------------------------------------------------
__global__ __launch_bounds__(512) void avg_kernel(
    const __half* __restrict__ E, const float* __restrict__ Inv,
    float* __restrict__ avg_out)
{
    __shared__ float sinv[H_];
    const int bt = blockIdx.x;
    const int b = bt / LO_, t = bt % LO_;
    const int tid = threadIdx.x;

    if (tid < H_) sinv[tid] = Inv[(size_t)(b * H_ + tid) * LO_ + t] * (1.f / H_);
    __syncthreads();

    float a0 = 0.f, a1 = 0.f, a2 = 0.f, a3 = 0.f;
    #pragma unroll
    for (int h = 0; h < H_; h++) {
        const __half2* Er = (const __half2*)(E + ((size_t)(b * H_ + h) * LO_ + t) * LS_);
        float sc = sinv[h];
        float2 u = __half22float2(Er[tid]);
        float2 w = __half22float2(Er[tid + 512]);
        a0 += u.x * sc; a1 += u.y * sc;
        a2 += w.x * sc; a3 += w.y * sc;
    }
    float2* A2 = (float2*)(avg_out + (size_t)bt * LS_);
    A2[tid]       = make_float2(a0, a1);
    A2[tid + 512] = make_float2(a2, a3);
}

// ---------------------------------------------------------------------------
// Launch
// ---------------------------------------------------------------------------
extern "C" void kernel_launch(void* const* d_in, const int* in_sizes, int n_in,
                              void* d_out, int out_size)
{
    (void)in_sizes; (void)n_in; (void)out_size;

    const float* V    = (const float*)d_in[0];
    const float* L    = (const float*)d_in[1];
    const float* O    = (const float*)d_in[2];
    const float* mask = (const float*)d_in[3];
    const float* w1   = (const float*)d_in[4];
    const float* b1   = (const float*)d_in[5];
    const float* w2   = (const float*)d_in[6];
    const float* b2   = (const float*)d_in[7];
    const float* ow   = (const float*)d_in[8];
    const float* ob   = (const float*)d_in[9];

    float* out = (float*)d_out;
    float* avg = out + (size_t)B_ * LO_ * E_;

    __half *Oh, *Vh, *Lh, *w1h, *w2h, *qq, *kv1, *kv2, *Eh, *ctxh, *owh;
    float* Inv;
    cudaGetSymbolAddress((void**)&Oh,   g_Oh);
    cudaGetSymbolAddress((void**)&Vh,   g_Vh);
    cudaGetSymbolAddress((void**)&Lh,   g_Lh);
    cudaGetSymbolAddress((void**)&w1h,  g_w1h);
    cudaGetSymbolAddress((void**)&w2h,  g_w2h);
    cudaGetSymbolAddress((void**)&ctxh, g_ctxh);
    cudaGetSymbolAddress((void**)&owh,  g_owh);
    cudaGetSymbolAddress((void**)&qq,   g_qq);
    cudaGetSymbolAddress((void**)&kv1,  g_kv1);
    cudaGetSymbolAddress((void**)&kv2,  g_kv2);
    cudaGetSymbolAddress((void**)&Eh,   g_Eh);
    cudaGetSymbolAddress((void**)&Inv,  g_inv);

    cudaFuncSetAttribute(proj_qkv,   cudaFuncAttributeMaxDynamicSharedMemorySize, SMEM_PROJ);
    cudaFuncSetAttribute(proj_out,   cudaFuncAttributeMaxDynamicSharedMemorySize, SMEM_PROJ);
    cudaFuncSetAttribute(attn_fused, cudaFuncAttributeMaxDynamicSharedMemorySize, SMEM_ATTN);

    // 1) Fused splits
    split_all<<<(ROW * (E_ / 4)) / 256, 256>>>(V, L, O, w1, w2, ow,
                                               Vh, Lh, Oh, w1h, w2h, owh);

    // 2) q/k/v projections
    dim3 gP(E2_ / 128, (B_ * LV_) / 128, 3);
    proj_qkv<<<gP, 256, SMEM_PROJ>>>(Oh, Vh, Lh, w1h, w2h, b1, b2, qq, kv1, kv2);

    // 3) Fused attention v5 (m-tile 64, 2 CTAs/SM)
    dim3 gA(LO_ / 64, Z_);     // 8 x 96
    attn_fused<<<gA, 512, SMEM_ATTN>>>(qq, kv1, kv2, mask, Eh, Inv, ctxh);

    // 4) Head-average
    avg_kernel<<<B_ * LO_, 512>>>(Eh, Inv, avg);

    // 5) Output projection (fp16 2-term)
    dim3 gO(E_ / 128, (B_ * LO_) / 128);
    proj_out<<<gO, 256, SMEM_PROJ>>>(ctxh, owh, ob, out);
}

// round 14
// speedup vs baseline: 1.3906x; 1.3906x over previous
#include <cuda_runtime.h>
#include <cuda_bf16.h>
#include <cuda_fp16.h>
#include <math.h>
#include <stdint.h>

// Problem dims
#define E_  768
#define H_  12
#define D_  64
#define B_  8
#define LO_ 512
#define LV_ 1024
#define LL_ 1024
#define LS_ 2048
#define Z_  (B_ * H_)     // 96
#define E2_ 1536

#define PADC 72                          // padded row stride for 64-wide tiles
#define TILE64B (128 * PADC * 2)         // 18432 B: one 128x64 fp16 tile
#define STGP (2 * TILE64B)               // proj stage: A + B = 36864
#define SMEM_PROJ (3 * STGP)             // 110592
// fused attention: 3 stages x (K + V) + 2 Q tiles (R12 config)
#define STGF (2 * TILE64B)               // 36864
#define SMEM_ATTN (3 * STGF + 2 * TILE64B)   // 147456
#define QOFF (3 * STGF)
#define RS2 (2 * E_)

// ---------------------------------------------------------------------------
// Scratch
// ---------------------------------------------------------------------------
__device__ __half g_Oh [(size_t)B_ * LO_ * E_];
__device__ __half g_Vh [(size_t)B_ * LV_ * E_];
__device__ __half g_Lh [(size_t)B_ * LL_ * E_];
__device__ __half g_w1h[(size_t)(3 * E_) * E_];
__device__ __half g_w2h[(size_t)(3 * E_) * E_];
__device__ __half g_ctxh[(size_t)B_ * LO_ * RS2];   // fp16 hi/lo planes
__device__ __half g_owh [(size_t)E_ * E_];

__device__ __half g_qq [(size_t)B_ * LO_ * E2_];
__device__ __half g_kv1[(size_t)B_ * LV_ * E2_];
__device__ __half g_kv2[(size_t)B_ * LL_ * E2_];
__device__ __half g_Eh [(size_t)Z_ * LO_ * LS_];
__device__ float  g_inv[(size_t)Z_ * LO_];

// ---------------------------------------------------------------------------
// Helpers
// ---------------------------------------------------------------------------
__device__ __forceinline__ uint32_t smem_u32(const void* p) {
    uint32_t a;
    asm("{ .reg .u64 t; cvta.to.shared.u64 t, %1; cvt.u32.u64 %0, t; }"
        : "=r"(a) : "l"(p));
    return a;
}
__device__ __forceinline__ void cpa16(uint32_t s, const void* g) {
    asm volatile("cp.async.cg.shared.global [%0], [%1], 16;" :: "r"(s), "l"(g));
}
__device__ __forceinline__ void ldm_x4(uint32_t& r0, uint32_t& r1, uint32_t& r2,
                                       uint32_t& r3, uint32_t addr) {
    asm volatile("ldmatrix.sync.aligned.m8n8.x4.shared.b16 {%0,%1,%2,%3}, [%4];"
        : "=r"(r0), "=r"(r1), "=r"(r2), "=r"(r3) : "r"(addr));
}
__device__ __forceinline__ void ldm_x4_t(uint32_t& r0, uint32_t& r1, uint32_t& r2,
                                         uint32_t& r3, uint32_t addr) {
    asm volatile("ldmatrix.sync.aligned.m8n8.x4.trans.shared.b16 {%0,%1,%2,%3}, [%4];"
        : "=r"(r0), "=r"(r1), "=r"(r2), "=r"(r3) : "r"(addr));
}
__device__ __forceinline__ void mma_hf(float* d, const uint32_t* a,
                                       uint32_t b0, uint32_t b1) {
    asm volatile(
        "mma.sync.aligned.m16n8k16.row.col.f32.f16.f16.f32 "
        "{%0,%1,%2,%3}, {%4,%5,%6,%7}, {%8,%9}, {%0,%1,%2,%3};"
        : "+f"(d[0]), "+f"(d[1]), "+f"(d[2]), "+f"(d[3])
        : "r"(a[0]), "r"(a[1]), "r"(a[2]), "r"(a[3]), "r"(b0), "r"(b1));
}
__device__ __forceinline__ void fsplit_hf(float x, __half& h, __half& l) {
    h = __float2half_rn(x);
    l = __float2half_rn(x - __half2float(h));
}

// ---------------------------------------------------------------------------
// Fused split: V,L,O,w1,w2,ow -> fp16 single plane.
// ---------------------------------------------------------------------------
#define RV 8192
#define RL 16384
#define RO 20480
#define RW1 22784
#define RW2 25088
#define ROW 25856
__global__ __launch_bounds__(256) void split_all(
    const float* __restrict__ V, const float* __restrict__ L,
    const float* __restrict__ O, const float* __restrict__ w1,
    const float* __restrict__ w2, const float* __restrict__ ow,
    __half* __restrict__ Vh, __half* __restrict__ Lh,
    __half* __restrict__ Oh, __half* __restrict__ w1h,
    __half* __restrict__ w2h, __half* __restrict__ owh)
{
    const int CP = E_ / 4;
    int gid = blockIdx.x * 256 + threadIdx.x;
    int r = gid / CP, c4 = (gid % CP) * 4;
    const float* x;
    __half* y;
    if      (r < RV)  { x = V;  y = Vh;  }
    else if (r < RL)  { x = L;  y = Lh;  r -= RV; }
    else if (r < RO)  { x = O;  y = Oh;  r -= RL; }
    else if (r < RW1) { x = w1; y = w1h; r -= RO; }
    else if (r < RW2) { x = w2; y = w2h; r -= RW1; }
    else if (r < ROW) { x = ow; y = owh; r -= RW2; }
    else return;
    float4 v = *(const float4*)(x + (size_t)r * E_ + c4);
    float vv[4] = {v.x, v.y, v.z, v.w};
    uint64_t hp = 0;
    #pragma unroll
    for (int i = 0; i < 4; i++)
        hp |= (uint64_t)__half_as_ushort(__float2half_rn(vv[i])) << (16 * i);
    *(uint64_t*)(y + (size_t)r * E_ + c4) = hp;
}

// ---------------------------------------------------------------------------
// q/k/v projections (fp16 1-plane, K'=768). FLAT grid: 1920 CTAs
// (384 q + 768 kv1 + 768 kv2), no dead blocks.
// ---------------------------------------------------------------------------
__global__ __launch_bounds__(256, 2) void proj_qkv(
    const __half* __restrict__ Oh, const __half* __restrict__ Vh,
    const __half* __restrict__ Lh,
    const __half* __restrict__ w1h, const __half* __restrict__ w2h,
    const float* __restrict__ b1, const float* __restrict__ b2,
    __half* __restrict__ qq, __half* __restrict__ kv1, __half* __restrict__ kv2)
{
    extern __shared__ char smx[];
    const uint32_t base = smem_u32(smx);
    const size_t WS = (size_t)E_ * E_;
    const __half *A, *W1, *W2;
    const float *bi1, *bi2;
    __half* out;
    int bid = blockIdx.x;
    int nb, mb;
    if (bid < 384) {
        nb = bid % 12; mb = bid / 12;
        A = Oh; W1 = w1h; W2 = w2h; bi1 = b1; bi2 = b2; out = qq;
    } else if (bid < 1152) {
        int idx = bid - 384;
        nb = idx % 12; mb = idx / 12;
        A = Vh; W1 = w1h + WS; W2 = w1h + 2 * WS;
        bi1 = b1 + E_; bi2 = b1 + 2 * E_; out = kv1;
    } else {
        int idx = bid - 1152;
        nb = idx % 12; mb = idx / 12;
        A = Lh; W1 = w2h + WS; W2 = w2h + 2 * WS;
        bi1 = b2 + E_; bi2 = b2 + 2 * E_; out = kv2;
    }
    const int n0 = nb * 128;
    const int m0 = mb * 128;
    const __half* Wb = (n0 < E_) ? W1 + (size_t)n0 * E_
                                 : W2 + (size_t)(n0 - E_) * E_;
    const float* biasb = (n0 < E_) ? bi1 + n0 : bi2 + (n0 - E_);

    const int tid  = threadIdx.x;
    const int warp = tid >> 5, lane = tid & 31;
    const int wm = warp >> 2, wn = warp & 3;

    const int rA = tid >> 3;
    const int c8 = (tid & 7) * 8;
    const __half* aP = A + (size_t)(m0 + rA) * E_ + c8;
    const __half* wP = Wb + (size_t)rA * E_ + c8;
    const uint32_t off0 = 2u * (rA * PADC + c8);

    #define PLOADH(j) do { \
        int _ko = (j) * 64; \
        uint32_t _sb = base + ((j) % 3) * STGP; \
        _Pragma("unroll") \
        for (int _i = 0; _i < 4; _i++) { \
            cpa16(_sb + off0 + _i * (2 * 32 * PADC), aP + _ko + (size_t)_i * 32 * E_); \
            cpa16(_sb + TILE64B + off0 + _i * (2 * 32 * PADC), wP + _ko + (size_t)_i * 32 * E_); \
        } \
        asm volatile("cp.async.commit_group;" ::: "memory"); \
    } while (0)

    PLOADH(0); PLOADH(1);

    const int lr = lane & 15;
    const int lh = (lane >> 4) * 8;

    float acc[4][4][4];
    #pragma unroll
    for (int i = 0; i < 4; i++)
        #pragma unroll
        for (int j = 0; j < 4; j++)
            #pragma unroll
            for (int q = 0; q < 4; q++) acc[i][j][q] = 0.f;

    const int NCHUNK = 12;
    for (int c = 0; c < NCHUNK; c++) {
        asm volatile("cp.async.wait_group 1;" ::: "memory");
        __syncthreads();
        if (c + 2 < NCHUNK) PLOADH(c + 2);
        else asm volatile("cp.async.commit_group;" ::: "memory");

        const uint32_t ab = base + (c % 3) * STGP;
        const uint32_t bb = ab + TILE64B;
        #pragma unroll
        for (int kf = 0; kf < 4; kf++) {
            uint32_t a[4][4];
            #pragma unroll
            for (int mi = 0; mi < 4; mi++)
                ldm_x4(a[mi][0], a[mi][1], a[mi][2], a[mi][3],
                       ab + 2u * ((wm * 64 + mi * 16 + lr) * PADC + kf * 16 + lh));
            uint32_t br[2][4];
            #pragma unroll
            for (int g = 0; g < 2; g++)
                ldm_x4(br[g][0], br[g][1], br[g][2], br[g][3],
                       bb + 2u * ((wn * 32 + g * 16 + lr) * PADC + kf * 16 + lh));
            #pragma unroll
            for (int mi = 0; mi < 4; mi++)
                #pragma unroll
                for (int g = 0; g < 2; g++)
                    #pragma unroll
                    for (int s = 0; s < 2; s++)
                        mma_hf(acc[mi][g * 2 + s], a[mi], br[g][s], br[g][s + 2]);
        }
    }
    #undef PLOADH

    const int er = lane >> 2;
    const int ec = (lane & 3) * 2;
    #pragma unroll
    for (int mi = 0; mi < 4; mi++) {
        #pragma unroll
        for (int ni = 0; ni < 4; ni++) {
            int m = m0 + wm * 64 + mi * 16 + er;
            int cl = wn * 32 + ni * 8 + ec;
            float bx = __ldg(biasb + cl), by = __ldg(biasb + cl + 1);
            *(__half2*)(out + (size_t)m * E2_ + n0 + cl) =
                __floats2half2_rn(acc[mi][ni][0] + bx, acc[mi][ni][1] + by);
            *(__half2*)(out + (size_t)(m + 8) * E2_ + n0 + cl) =
                __floats2half2_rn(acc[mi][ni][2] + bx, acc[mi][ni][3] + by);
        }
    }
}

// ---------------------------------------------------------------------------
// Output projection (fp16 2-term, K'=1536): unchanged from R12.
// ---------------------------------------------------------------------------
__global__ __launch_bounds__(256, 2) void proj_out(
    const __half* __restrict__ A,
    const __half* __restrict__ W,
    const float* __restrict__ ob, float* __restrict__ out)
{
    extern __shared__ char smx[];
    const uint32_t base = smem_u32(smx);
    const int n0 = blockIdx.x * 128;
    const int m0 = blockIdx.y * 128;
    const __half* Wb = W + (size_t)n0 * E_;
    const float* biasb = ob + n0;

    const int tid  = threadIdx.x;
    const int warp = tid >> 5, lane = tid & 31;
    const int wm = warp >> 2, wn = warp & 3;

    const int rA = tid >> 3;
    const int c8 = (tid & 7) * 8;
    const __half* aP = A + (size_t)(m0 + rA) * RS2 + c8;
    const __half* wP = Wb + (size_t)rA * E_ + c8;
    const uint32_t off0 = 2u * (rA * PADC + c8);

    #define PLOAD(j) do { \
        int _t = (j) / 12, _ko = ((j) % 12) * 64; \
        int _ap = _t * E_; \
        uint32_t _sb = base + ((j) % 3) * STGP; \
        _Pragma("unroll") \
        for (int _i = 0; _i < 4; _i++) { \
            cpa16(_sb + off0 + _i * (2 * 32 * PADC), aP + _ap + _ko + (size_t)_i * 32 * RS2); \
            cpa16(_sb + TILE64B + off0 + _i * (2 * 32 * PADC), wP + _ko + (size_t)_i * 32 * E_); \
        } \
        asm volatile("cp.async.commit_group;" ::: "memory"); \
    } while (0)

    PLOAD(0); PLOAD(1);

    const int lr = lane & 15;
    const int lh = (lane >> 4) * 8;

    float acc[4][4][4];
    #pragma unroll
    for (int i = 0; i < 4; i++)
        #pragma unroll
        for (int j = 0; j < 4; j++)
            #pragma unroll
            for (int q = 0; q < 4; q++) acc[i][j][q] = 0.f;

    const int NCHUNK = 24;
    for (int c = 0; c < NCHUNK; c++) {
        asm volatile("cp.async.wait_group 1;" ::: "memory");
        __syncthreads();
        if (c + 2 < NCHUNK) PLOAD(c + 2);
        else asm volatile("cp.async.commit_group;" ::: "memory");

        const uint32_t ab = base + (c % 3) * STGP;
        const uint32_t bb = ab + TILE64B;
        #pragma unroll
        for (int kf = 0; kf < 4; kf++) {
            uint32_t a[4][4];
            #pragma unroll
            for (int mi = 0; mi < 4; mi++)
                ldm_x4(a[mi][0], a[mi][1], a[mi][2], a[mi][3],
                       ab + 2u * ((wm * 64 + mi * 16 + lr) * PADC + kf * 16 + lh));
            uint32_t br[2][4];
            #pragma unroll
            for (int g = 0; g < 2; g++)
                ldm_x4(br[g][0], br[g][1], br[g][2], br[g][3],
                       bb + 2u * ((wn * 32 + g * 16 + lr) * PADC + kf * 16 + lh));
            #pragma unroll
            for (int mi = 0; mi < 4; mi++)
                #pragma unroll
                for (int g = 0; g < 2; g++)
                    #pragma unroll
                    for (int s = 0; s < 2; s++)
                        mma_hf(acc[mi][g * 2 + s], a[mi], br[g][s], br[g][s + 2]);
        }
    }
    #undef PLOAD

    const int er = lane >> 2;
    const int ec = (lane & 3) * 2;
    #pragma unroll
    for (int mi = 0; mi < 4; mi++) {
        #pragma unroll
        for (int ni = 0; ni < 4; ni++) {
            int m = m0 + wm * 64 + mi * 16 + er;
            int cl = wn * 32 + ni * 8 + ec;
            float bx = __ldg(biasb + cl), by = __ldg(biasb + cl + 1);
            *(float2*)(out + (size_t)m * E_ + n0 + cl) =
                make_float2(acc[mi][ni][0] + bx, acc[mi][ni][1] + by);
            *(float2*)(out + (size_t)(m + 8) * E_ + n0 + cl) =
                make_float2(acc[mi][ni][2] + bx, acc[mi][ni][3] + by);
        }
    }
}

// ---------------------------------------------------------------------------
// Fused attention (R12 v4, known-good): 512 threads, 16 warps = 8(M) x 2(s-
// half), 3 stages, ONE sync per tile, m-tile 128. grid (4, 96).
// ---------------------------------------------------------------------------
__global__ __launch_bounds__(512) void attn_fused(
    const __half* __restrict__ Q, const __half* __restrict__ KV1,
    const __half* __restrict__ KV2,
    const float* __restrict__ mask,
    __half* __restrict__ Eo, float* __restrict__ Inv,
    __half* __restrict__ Cs)
{
    extern __shared__ char smx[];
    const uint32_t base = smem_u32(smx);

    const int tid  = threadIdx.x;
    const int warp = tid >> 5, lane = tid & 31;
    const int mw = warp & 7;
    const int nh = warp >> 3;
    const int z = blockIdx.y;
    const int b = z / H_, h = z % H_;
    const int m0 = blockIdx.x * 128;

    int rk[2];
    const int ckc = (tid & 7) * 8;
    rk[0] = tid >> 3;
    rk[1] = (tid + 512) >> 3;

    #pragma unroll
    for (int i = 0; i < 4; i++) {
        int idx = tid + i * 512;
        int tile = idx >> 10;
        int w = idx & 1023;
        int r = w >> 3, c = (w & 7) * 8;
        cpa16(base + QOFF + tile * TILE64B + 2u * (r * PADC + c),
              Q + (size_t)(b * LO_ + m0 + r) * E2_ + tile * E_ + h * D_ + c);
    }

    #define AKV(j) do { \
        const __half* _kb = ((j) < 8) ? KV1 : KV2; \
        int _s0 = (((j) < 8) ? (j) : ((j) - 8)) * 128; \
        uint32_t _sb = base + ((j) % 3) * STGF; \
        _Pragma("unroll") \
        for (int _i = 0; _i < 2; _i++) { \
            const __half* _row = _kb + (size_t)(b * LV_ + _s0 + rk[_i]) * E2_ + h * D_ + ckc; \
            uint32_t _o = 2u * (rk[_i] * PADC + ckc); \
            cpa16(_sb + _o, _row); \
            cpa16(_sb + TILE64B + _o, _row + E_); \
        } \
        asm volatile("cp.async.commit_group;" ::: "memory"); \
    } while (0)

    AKV(0);
    AKV(1);

    const int lr = lane & 15;
    const int lh = (lane >> 4) * 8;
    const int er = lane >> 2;
    const int ec = (lane & 3) * 2;
    const int tg  = lane >> 3;
    const int tlr = lane & 7;
    const int tko = (tg & 1) * 8;
    const int tno = (tg >> 1) * 8;

    const int row0 = m0 + mw * 16 + er;
    const int row1 = row0 + 8;

    float acc_c[8][4];
    #pragma unroll
    for (int j = 0; j < 8; j++)
        #pragma unroll
        for (int q = 0; q < 4; q++) acc_c[j][q] = 0.f;

    uint32_t qf[4][4];
    float rs0 = 0.f, rs1 = 0.f;

    for (int nt = 0; nt < 16; nt++) {
        asm volatile("cp.async.wait_group 1;" ::: "memory");
        __syncthreads();
        if (nt + 2 < 16) AKV(nt + 2);
        else asm volatile("cp.async.commit_group;" ::: "memory");

        if (nt == 0 || nt == 8) {
            uint32_t qb = base + QOFF + (nt == 8 ? TILE64B : 0);
            #pragma unroll
            for (int kf = 0; kf < 4; kf++)
                ldm_x4(qf[kf][0], qf[kf][1], qf[kf][2], qf[kf][3],
                       qb + 2u * ((mw * 16 + lr) * PADC + kf * 16 + lh));
        }

        const uint32_t kb = base + (nt % 3) * STGF;
        const uint32_t vb = kb + TILE64B;

        float acc_s[8][4];
        #pragma unroll
        for (int j = 0; j < 8; j++)
            #pragma unroll
            for (int q = 0; q < 4; q++) acc_s[j][q] = 0.f;

        #pragma unroll
        for (int kf = 0; kf < 4; kf++) {
            #pragma unroll
            for (int g = 0; g < 4; g++) {
                uint32_t br[4];
                ldm_x4(br[0], br[1], br[2], br[3],
                       kb + 2u * ((nh * 64 + g * 16 + lr) * PADC + kf * 16 + lh));
                mma_hf(acc_s[2 * g],     qf[kf], br[0], br[2]);
                mma_hf(acc_s[2 * g + 1], qf[kf], br[1], br[3]);
            }
        }

        const int nbase = nt * 128 + nh * 64;
        uint32_t ph[8][2];
        #pragma unroll
        for (int j = 0; j < 8; j++) {
            int n = nbase + j * 8 + ec;
            float2 mk0 = *(const float2*)(mask + (size_t)row0 * LS_ + n);
            float2 mk1 = *(const float2*)(mask + (size_t)row1 * LS_ + n);
            float e0 = __expf(fminf(acc_s[j][0] * 0.125f + mk0.x, 11.f));
            float e1 = __expf(fminf(acc_s[j][1] * 0.125f + mk0.y, 11.f));
            float e2 = __expf(fminf(acc_s[j][2] * 0.125f + mk1.x, 11.f));
            float e3 = __expf(fminf(acc_s[j][3] * 0.125f + mk1.y, 11.f));
            __half2 u01 = __floats2half2_rn(e0, e1);
            __half2 u23 = __floats2half2_rn(e2, e3);
            ph[j][0] = *(uint32_t*)&u01;
            ph[j][1] = *(uint32_t*)&u23;
            *(__half2*)(Eo + ((size_t)z * LO_ + row0) * LS_ + n) = u01;
            *(__half2*)(Eo + ((size_t)z * LO_ + row1) * LS_ + n) = u23;
            rs0 += e0 + e1;
            rs1 += e2 + e3;
        }

        #pragma unroll
        for (int kt = 0; kt < 4; kt++) {
            uint32_t pa[4] = {ph[2 * kt][0], ph[2 * kt][1],
                              ph[2 * kt + 1][0], ph[2 * kt + 1][1]};
            #pragma unroll
            for (int g = 0; g < 4; g++) {
                uint32_t rb[4];
                ldm_x4_t(rb[0], rb[1], rb[2], rb[3],
                         vb + 2u * ((nh * 64 + kt * 16 + tko + tlr) * PADC + g * 16 + tno));
                mma_hf(acc_c[2 * g],     pa, rb[0], rb[1]);
                mma_hf(acc_c[2 * g + 1], pa, rb[2], rb[3]);
            }
        }
    }
    #undef AKV

    rs0 += __shfl_xor_sync(~0u, rs0, 1);
    rs0 += __shfl_xor_sync(~0u, rs0, 2);
    rs1 += __shfl_xor_sync(~0u, rs1, 1);
    rs1 += __shfl_xor_sync(~0u, rs1, 2);

    __syncthreads();

    float* srs = (float*)smx;
    if ((lane & 3) == 0) {
        srs[(warp * 8 + er) * 2 + 0] = rs0;
        srs[(warp * 8 + er) * 2 + 1] = rs1;
    }
    if (nh == 1) {
        float* pane = (float*)(smx + 1024) + mw * 1024;
        #pragma unroll
        for (int j = 0; j < 8; j++)
            #pragma unroll
            for (int q = 0; q < 4; q++)
                pane[(j * 4 + q) * 32 + lane] = acc_c[j][q];
    }
    __syncthreads();

    if (nh == 0) {
        float pr0 = srs[((warp + 8) * 8 + er) * 2 + 0];
        float pr1 = srs[((warp + 8) * 8 + er) * 2 + 1];
        float inv0 = 1.f / (rs0 + pr0);
        float inv1 = 1.f / (rs1 + pr1);
        if ((lane & 3) == 0) {
            Inv[(size_t)z * LO_ + row0] = inv0;
            Inv[(size_t)z * LO_ + row1] = inv1;
        }
        const float* pane = (const float*)(smx + 1024) + mw * 1024;
        #pragma unroll
        for (int j = 0; j < 8; j++)
            #pragma unroll
            for (int q = 0; q < 4; q++)
                acc_c[j][q] += pane[(j * 4 + q) * 32 + lane];

        #pragma unroll
        for (int j = 0; j < 8; j++) {
            int nl = j * 8 + ec;
            __half* d0 = Cs + (size_t)(b * LO_ + row0) * RS2 + h * D_ + nl;
            __half* d1 = Cs + (size_t)(b * LO_ + row1) * RS2 + h * D_ + nl;
            __half h0, l0, h1, l1;
            fsplit_hf(acc_c[j][0] * inv0, h0, l0);
            fsplit_hf(acc_c[j][1] * inv0, h1, l1);
            *(__half2*)(d0)      = __half2(h0, h1);
            *(__half2*)(d0 + E_) = __half2(l0, l1);
            fsplit_hf(acc_c[j][2] * inv1, h0, l0);
            fsplit_hf(acc_c[j][3] * inv1, h1, l1);
            *(__half2*)(d1)      = __half2(h0, h1);
            *(__half2*)(d1 + E_) = __half2(l0, l1);
        }
    }
}

// ---------------------------------------------------------------------------
// Head-average: pure stream.
// ---------------------------------------------------------------------------
__global__ __launch_bounds__(512) void avg_kernel(
    const __half* __restrict__ E, const float* __restrict__ Inv,
    float* __restrict__ avg_out)
{
    __shared__ float sinv[H_];
    const int bt = blockIdx.x;
    const int b = bt / LO_, t = bt % LO_;
    const int tid = threadIdx.x;

    if (tid < H_) sinv[tid] = Inv[(size_t)(b * H_ + tid) * LO_ + t] * (1.f / H_);
    __syncthreads();

    float a0 = 0.f, a1 = 0.f, a2 = 0.f, a3 = 0.f;
    #pragma unroll
    for (int h = 0; h < H_; h++) {
        const __half2* Er = (const __half2*)(E + ((size_t)(b * H_ + h) * LO_ + t) * LS_);
        float sc = sinv[h];
        float2 u = __half22float2(Er[tid]);
        float2 w = __half22float2(Er[tid + 512]);
        a0 += u.x * sc; a1 += u.y * sc;
        a2 += w.x * sc; a3 += w.y * sc;
    }
    float2* A2 = (float2*)(avg_out + (size_t)bt * LS_);
    A2[tid]       = make_float2(a0, a1);
    A2[tid + 512] = make_float2(a2, a3);
}

// ---------------------------------------------------------------------------
// Launch
// ---------------------------------------------------------------------------
extern "C" void kernel_launch(void* const* d_in, const int* in_sizes, int n_in,
                              void* d_out, int out_size)
{
    (void)in_sizes; (void)n_in; (void)out_size;

    const float* V    = (const float*)d_in[0];
    const float* L    = (const float*)d_in[1];
    const float* O    = (const float*)d_in[2];
    const float* mask = (const float*)d_in[3];
    const float* w1   = (const float*)d_in[4];
    const float* b1   = (const float*)d_in[5];
    const float* w2   = (const float*)d_in[6];
    const float* b2   = (const float*)d_in[7];
    const float* ow   = (const float*)d_in[8];
    const float* ob   = (const float*)d_in[9];

    float* out = (float*)d_out;
    float* avg = out + (size_t)B_ * LO_ * E_;

    __half *Oh, *Vh, *Lh, *w1h, *w2h, *qq, *kv1, *kv2, *Eh, *ctxh, *owh;
    float* Inv;
    cudaGetSymbolAddress((void**)&Oh,   g_Oh);
    cudaGetSymbolAddress((void**)&Vh,   g_Vh);
    cudaGetSymbolAddress((void**)&Lh,   g_Lh);
    cudaGetSymbolAddress((void**)&w1h,  g_w1h);
    cudaGetSymbolAddress((void**)&w2h,  g_w2h);
    cudaGetSymbolAddress((void**)&ctxh, g_ctxh);
    cudaGetSymbolAddress((void**)&owh,  g_owh);
    cudaGetSymbolAddress((void**)&qq,   g_qq);
    cudaGetSymbolAddress((void**)&kv1,  g_kv1);
    cudaGetSymbolAddress((void**)&kv2,  g_kv2);
    cudaGetSymbolAddress((void**)&Eh,   g_Eh);
    cudaGetSymbolAddress((void**)&Inv,  g_inv);

    cudaFuncSetAttribute(proj_qkv,   cudaFuncAttributeMaxDynamicSharedMemorySize, SMEM_PROJ);
    cudaFuncSetAttribute(proj_out,   cudaFuncAttributeMaxDynamicSharedMemorySize, SMEM_PROJ);
    cudaFuncSetAttribute(attn_fused, cudaFuncAttributeMaxDynamicSharedMemorySize, SMEM_ATTN);

    // 1) Fused splits
    split_all<<<(ROW * (E_ / 4)) / 256, 256>>>(V, L, O, w1, w2, ow,
                                               Vh, Lh, Oh, w1h, w2h, owh);

    // 2) q/k/v projections (flat grid, 1920 CTAs, no dead blocks)
    proj_qkv<<<1920, 256, SMEM_PROJ>>>(Oh, Vh, Lh, w1h, w2h, b1, b2, qq, kv1, kv2);

    // 3) Fused attention (R12 config)
    dim3 gA(LO_ / 128, Z_);    // 4 x 96
    attn_fused<<<gA, 512, SMEM_ATTN>>>(qq, kv1, kv2, mask, Eh, Inv, ctxh);

    // 4) Head-average
    avg_kernel<<<B_ * LO_, 512>>>(Eh, Inv, avg);

    // 5) Output projection (fp16 2-term)
    dim3 gO(E_ / 128, (B_ * LO_) / 128);
    proj_out<<<gO, 256, SMEM_PROJ>>>(ctxh, owh, ob, out);
}

// round 15
// speedup vs baseline: 1.3975x; 1.0049x over previous
#include <cuda_runtime.h>
#include <cuda_bf16.h>
#include <cuda_fp16.h>
#include <math.h>
#include <stdint.h>

// Problem dims
#define E_  768
#define H_  12
#define D_  64
#define B_  8
#define LO_ 512
#define LV_ 1024
#define LL_ 1024
#define LS_ 2048
#define Z_  (B_ * H_)     // 96
#define E2_ 1536

#define PADC 72                          // padded row stride for 64-wide tiles
#define TILE64B (128 * PADC * 2)         // 18432 B: one 128x64 fp16 tile
#define STGP (2 * TILE64B)               // proj stage: A + B = 36864
#define SMEM_PROJ (3 * STGP)             // 110592
// fused attention: 3 stages x (K + V) + 2 Q tiles (R12 config)
#define STGF (2 * TILE64B)               // 36864
#define SMEM_ATTN (3 * STGF + 2 * TILE64B)   // 147456
#define QOFF (3 * STGF)
#define RS2 (2 * E_)

// ---------------------------------------------------------------------------
// Scratch
// ---------------------------------------------------------------------------
__device__ __half g_Oh [(size_t)B_ * LO_ * E_];
__device__ __half g_Vh [(size_t)B_ * LV_ * E_];
__device__ __half g_Lh [(size_t)B_ * LL_ * E_];
__device__ __half g_w1h[(size_t)(3 * E_) * E_];
__device__ __half g_w2h[(size_t)(3 * E_) * E_];
__device__ __half g_ctxh[(size_t)B_ * LO_ * RS2];   // fp16 hi/lo planes
__device__ __half g_owh [(size_t)E_ * E_];

__device__ __half g_qq [(size_t)B_ * LO_ * E2_];
__device__ __half g_kv1[(size_t)B_ * LV_ * E2_];
__device__ __half g_kv2[(size_t)B_ * LL_ * E2_];
__device__ __half g_Eh [(size_t)Z_ * LO_ * LS_];
__device__ float  g_inv[(size_t)Z_ * LO_];

// ---------------------------------------------------------------------------
// Helpers
// ---------------------------------------------------------------------------
__device__ __forceinline__ uint32_t smem_u32(const void* p) {
    uint32_t a;
    asm("{ .reg .u64 t; cvta.to.shared.u64 t, %1; cvt.u32.u64 %0, t; }"
        : "=r"(a) : "l"(p));
    return a;
}
__device__ __forceinline__ void cpa16(uint32_t s, const void* g) {
    asm volatile("cp.async.cg.shared.global [%0], [%1], 16;" :: "r"(s), "l"(g));
}
__device__ __forceinline__ void ldm_x4(uint32_t& r0, uint32_t& r1, uint32_t& r2,
                                       uint32_t& r3, uint32_t addr) {
    asm volatile("ldmatrix.sync.aligned.m8n8.x4.shared.b16 {%0,%1,%2,%3}, [%4];"
        : "=r"(r0), "=r"(r1), "=r"(r2), "=r"(r3) : "r"(addr));
}
__device__ __forceinline__ void ldm_x4_t(uint32_t& r0, uint32_t& r1, uint32_t& r2,
                                         uint32_t& r3, uint32_t addr) {
    asm volatile("ldmatrix.sync.aligned.m8n8.x4.trans.shared.b16 {%0,%1,%2,%3}, [%4];"
        : "=r"(r0), "=r"(r1), "=r"(r2), "=r"(r3) : "r"(addr));
}
__device__ __forceinline__ void mma_hf(float* d, const uint32_t* a,
                                       uint32_t b0, uint32_t b1) {
    asm volatile(
        "mma.sync.aligned.m16n8k16.row.col.f32.f16.f16.f32 "
        "{%0,%1,%2,%3}, {%4,%5,%6,%7}, {%8,%9}, {%0,%1,%2,%3};"
        : "+f"(d[0]), "+f"(d[1]), "+f"(d[2]), "+f"(d[3])
        : "r"(a[0]), "r"(a[1]), "r"(a[2]), "r"(a[3]), "r"(b0), "r"(b1));
}
__device__ __forceinline__ void fsplit_hf(float x, __half& h, __half& l) {
    h = __float2half_rn(x);
    l = __float2half_rn(x - __half2float(h));
}

// ---------------------------------------------------------------------------
// Fused split: V,L,O,w1,w2,ow -> fp16 single plane.
// ---------------------------------------------------------------------------
#define RV 8192
#define RL 16384
#define RO 20480
#define RW1 22784
#define RW2 25088
#define ROW 25856
__global__ __launch_bounds__(256) void split_all(
    const float* __restrict__ V, const float* __restrict__ L,
    const float* __restrict__ O, const float* __restrict__ w1,
    const float* __restrict__ w2, const float* __restrict__ ow,
    __half* __restrict__ Vh, __half* __restrict__ Lh,
    __half* __restrict__ Oh, __half* __restrict__ w1h,
    __half* __restrict__ w2h, __half* __restrict__ owh)
{
    const int CP = E_ / 4;
    int gid = blockIdx.x * 256 + threadIdx.x;
    int r = gid / CP, c4 = (gid % CP) * 4;
    const float* x;
    __half* y;
    if      (r < RV)  { x = V;  y = Vh;  }
    else if (r < RL)  { x = L;  y = Lh;  r -= RV; }
    else if (r < RO)  { x = O;  y = Oh;  r -= RL; }
    else if (r < RW1) { x = w1; y = w1h; r -= RO; }
    else if (r < RW2) { x = w2; y = w2h; r -= RW1; }
    else if (r < ROW) { x = ow; y = owh; r -= RW2; }
    else return;
    float4 v = *(const float4*)(x + (size_t)r * E_ + c4);
    float vv[4] = {v.x, v.y, v.z, v.w};
    uint64_t hp = 0;
    #pragma unroll
    for (int i = 0; i < 4; i++)
        hp |= (uint64_t)__half_as_ushort(__float2half_rn(vv[i])) << (16 * i);
    *(uint64_t*)(y + (size_t)r * E_ + c4) = hp;
}

// ---------------------------------------------------------------------------
// q/k/v projections (fp16 1-plane, K'=768). Flat grid, 1920 CTAs.
// ---------------------------------------------------------------------------
__global__ __launch_bounds__(256, 2) void proj_qkv(
    const __half* __restrict__ Oh, const __half* __restrict__ Vh,
    const __half* __restrict__ Lh,
    const __half* __restrict__ w1h, const __half* __restrict__ w2h,
    const float* __restrict__ b1, const float* __restrict__ b2,
    __half* __restrict__ qq, __half* __restrict__ kv1, __half* __restrict__ kv2)
{
    extern __shared__ char smx[];
    const uint32_t base = smem_u32(smx);
    const size_t WS = (size_t)E_ * E_;
    const __half *A, *W1, *W2;
    const float *bi1, *bi2;
    __half* out;
    int bid = blockIdx.x;
    int nb, mb;
    if (bid < 384) {
        nb = bid % 12; mb = bid / 12;
        A = Oh; W1 = w1h; W2 = w2h; bi1 = b1; bi2 = b2; out = qq;
    } else if (bid < 1152) {
        int idx = bid - 384;
        nb = idx % 12; mb = idx / 12;
        A = Vh; W1 = w1h + WS; W2 = w1h + 2 * WS;
        bi1 = b1 + E_; bi2 = b1 + 2 * E_; out = kv1;
    } else {
        int idx = bid - 1152;
        nb = idx % 12; mb = idx / 12;
        A = Lh; W1 = w2h + WS; W2 = w2h + 2 * WS;
        bi1 = b2 + E_; bi2 = b2 + 2 * E_; out = kv2;
    }
    const int n0 = nb * 128;
    const int m0 = mb * 128;
    const __half* Wb = (n0 < E_) ? W1 + (size_t)n0 * E_
                                 : W2 + (size_t)(n0 - E_) * E_;
    const float* biasb = (n0 < E_) ? bi1 + n0 : bi2 + (n0 - E_);

    const int tid  = threadIdx.x;
    const int warp = tid >> 5, lane = tid & 31;
    const int wm = warp >> 2, wn = warp & 3;

    const int rA = tid >> 3;
    const int c8 = (tid & 7) * 8;
    const __half* aP = A + (size_t)(m0 + rA) * E_ + c8;
    const __half* wP = Wb + (size_t)rA * E_ + c8;
    const uint32_t off0 = 2u * (rA * PADC + c8);

    #define PLOADH(j) do { \
        int _ko = (j) * 64; \
        uint32_t _sb = base + ((j) % 3) * STGP; \
        _Pragma("unroll") \
        for (int _i = 0; _i < 4; _i++) { \
            cpa16(_sb + off0 + _i * (2 * 32 * PADC), aP + _ko + (size_t)_i * 32 * E_); \
            cpa16(_sb + TILE64B + off0 + _i * (2 * 32 * PADC), wP + _ko + (size_t)_i * 32 * E_); \
        } \
        asm volatile("cp.async.commit_group;" ::: "memory"); \
    } while (0)

    PLOADH(0); PLOADH(1);

    const int lr = lane & 15;
    const int lh = (lane >> 4) * 8;

    float acc[4][4][4];
    #pragma unroll
    for (int i = 0; i < 4; i++)
        #pragma unroll
        for (int j = 0; j < 4; j++)
            #pragma unroll
            for (int q = 0; q < 4; q++) acc[i][j][q] = 0.f;

    const int NCHUNK = 12;
    for (int c = 0; c < NCHUNK; c++) {
        asm volatile("cp.async.wait_group 1;" ::: "memory");
        __syncthreads();
        if (c + 2 < NCHUNK) PLOADH(c + 2);
        else asm volatile("cp.async.commit_group;" ::: "memory");

        const uint32_t ab = base + (c % 3) * STGP;
        const uint32_t bb = ab + TILE64B;
        #pragma unroll
        for (int kf = 0; kf < 4; kf++) {
            uint32_t a[4][4];
            #pragma unroll
            for (int mi = 0; mi < 4; mi++)
                ldm_x4(a[mi][0], a[mi][1], a[mi][2], a[mi][3],
                       ab + 2u * ((wm * 64 + mi * 16 + lr) * PADC + kf * 16 + lh));
            uint32_t br[2][4];
            #pragma unroll
            for (int g = 0; g < 2; g++)
                ldm_x4(br[g][0], br[g][1], br[g][2], br[g][3],
                       bb + 2u * ((wn * 32 + g * 16 + lr) * PADC + kf * 16 + lh));
            #pragma unroll
            for (int mi = 0; mi < 4; mi++)
                #pragma unroll
                for (int g = 0; g < 2; g++)
                    #pragma unroll
                    for (int s = 0; s < 2; s++)
                        mma_hf(acc[mi][g * 2 + s], a[mi], br[g][s], br[g][s + 2]);
        }
    }
    #undef PLOADH

    const int er = lane >> 2;
    const int ec = (lane & 3) * 2;
    #pragma unroll
    for (int mi = 0; mi < 4; mi++) {
        #pragma unroll
        for (int ni = 0; ni < 4; ni++) {
            int m = m0 + wm * 64 + mi * 16 + er;
            int cl = wn * 32 + ni * 8 + ec;
            float bx = __ldg(biasb + cl), by = __ldg(biasb + cl + 1);
            *(__half2*)(out + (size_t)m * E2_ + n0 + cl) =
                __floats2half2_rn(acc[mi][ni][0] + bx, acc[mi][ni][1] + by);
            *(__half2*)(out + (size_t)(m + 8) * E2_ + n0 + cl) =
                __floats2half2_rn(acc[mi][ni][2] + bx, acc[mi][ni][3] + by);
        }
    }
}

// ---------------------------------------------------------------------------
// Output projection (fp16 2-term, K'=1536).
// ---------------------------------------------------------------------------
__global__ __launch_bounds__(256, 2) void proj_out(
    const __half* __restrict__ A,
    const __half* __restrict__ W,
    const float* __restrict__ ob, float* __restrict__ out)
{
    extern __shared__ char smx[];
    const uint32_t base = smem_u32(smx);
    const int n0 = blockIdx.x * 128;
    const int m0 = blockIdx.y * 128;
    const __half* Wb = W + (size_t)n0 * E_;
    const float* biasb = ob + n0;

    const int tid  = threadIdx.x;
    const int warp = tid >> 5, lane = tid & 31;
    const int wm = warp >> 2, wn = warp & 3;

    const int rA = tid >> 3;
    const int c8 = (tid & 7) * 8;
    const __half* aP = A + (size_t)(m0 + rA) * RS2 + c8;
    const __half* wP = Wb + (size_t)rA * E_ + c8;
    const uint32_t off0 = 2u * (rA * PADC + c8);

    #define PLOAD(j) do { \
        int _t = (j) / 12, _ko = ((j) % 12) * 64; \
        int _ap = _t * E_; \
        uint32_t _sb = base + ((j) % 3) * STGP; \
        _Pragma("unroll") \
        for (int _i = 0; _i < 4; _i++) { \
            cpa16(_sb + off0 + _i * (2 * 32 * PADC), aP + _ap + _ko + (size_t)_i * 32 * RS2); \
            cpa16(_sb + TILE64B + off0 + _i * (2 * 32 * PADC), wP + _ko + (size_t)_i * 32 * E_); \
        } \
        asm volatile("cp.async.commit_group;" ::: "memory"); \
    } while (0)

    PLOAD(0); PLOAD(1);

    const int lr = lane & 15;
    const int lh = (lane >> 4) * 8;

    float acc[4][4][4];
    #pragma unroll
    for (int i = 0; i < 4; i++)
        #pragma unroll
        for (int j = 0; j < 4; j++)
            #pragma unroll
            for (int q = 0; q < 4; q++) acc[i][j][q] = 0.f;

    const int NCHUNK = 24;
    for (int c = 0; c < NCHUNK; c++) {
        asm volatile("cp.async.wait_group 1;" ::: "memory");
        __syncthreads();
        if (c + 2 < NCHUNK) PLOAD(c + 2);
        else asm volatile("cp.async.commit_group;" ::: "memory");

        const uint32_t ab = base + (c % 3) * STGP;
        const uint32_t bb = ab + TILE64B;
        #pragma unroll
        for (int kf = 0; kf < 4; kf++) {
            uint32_t a[4][4];
            #pragma unroll
            for (int mi = 0; mi < 4; mi++)
                ldm_x4(a[mi][0], a[mi][1], a[mi][2], a[mi][3],
                       ab + 2u * ((wm * 64 + mi * 16 + lr) * PADC + kf * 16 + lh));
            uint32_t br[2][4];
            #pragma unroll
            for (int g = 0; g < 2; g++)
                ldm_x4(br[g][0], br[g][1], br[g][2], br[g][3],
                       bb + 2u * ((wn * 32 + g * 16 + lr) * PADC + kf * 16 + lh));
            #pragma unroll
            for (int mi = 0; mi < 4; mi++)
                #pragma unroll
                for (int g = 0; g < 2; g++)
                    #pragma unroll
                    for (int s = 0; s < 2; s++)
                        mma_hf(acc[mi][g * 2 + s], a[mi], br[g][s], br[g][s + 2]);
        }
    }
    #undef PLOAD

    const int er = lane >> 2;
    const int ec = (lane & 3) * 2;
    #pragma unroll
    for (int mi = 0; mi < 4; mi++) {
        #pragma unroll
        for (int ni = 0; ni < 4; ni++) {
            int m = m0 + wm * 64 + mi * 16 + er;
            int cl = wn * 32 + ni * 8 + ec;
            float bx = __ldg(biasb + cl), by = __ldg(biasb + cl + 1);
            *(float2*)(out + (size_t)m * E_ + n0 + cl) =
                make_float2(acc[mi][ni][0] + bx, acc[mi][ni][1] + by);
            *(float2*)(out + (size_t)(m + 8) * E_ + n0 + cl) =
                make_float2(acc[mi][ni][2] + bx, acc[mi][ni][3] + by);
        }
    }
}

// ---------------------------------------------------------------------------
// Fused attention (R12 v4 config, known-good). grid (4, 96), 512 threads.
// ---------------------------------------------------------------------------
__global__ __launch_bounds__(512) void attn_fused(
    const __half* __restrict__ Q, const __half* __restrict__ KV1,
    const __half* __restrict__ KV2,
    const float* __restrict__ mask,
    __half* __restrict__ Eo, float* __restrict__ Inv,
    __half* __restrict__ Cs)
{
    extern __shared__ char smx[];
    const uint32_t base = smem_u32(smx);

    const int tid  = threadIdx.x;
    const int warp = tid >> 5, lane = tid & 31;
    const int mw = warp & 7;
    const int nh = warp >> 3;
    const int z = blockIdx.y;
    const int b = z / H_, h = z % H_;
    const int m0 = blockIdx.x * 128;

    int rk[2];
    const int ckc = (tid & 7) * 8;
    rk[0] = tid >> 3;
    rk[1] = (tid + 512) >> 3;

    #pragma unroll
    for (int i = 0; i < 4; i++) {
        int idx = tid + i * 512;
        int tile = idx >> 10;
        int w = idx & 1023;
        int r = w >> 3, c = (w & 7) * 8;
        cpa16(base + QOFF + tile * TILE64B + 2u * (r * PADC + c),
              Q + (size_t)(b * LO_ + m0 + r) * E2_ + tile * E_ + h * D_ + c);
    }

    #define AKV(j) do { \
        const __half* _kb = ((j) < 8) ? KV1 : KV2; \
        int _s0 = (((j) < 8) ? (j) : ((j) - 8)) * 128; \
        uint32_t _sb = base + ((j) % 3) * STGF; \
        _Pragma("unroll") \
        for (int _i = 0; _i < 2; _i++) { \
            const __half* _row = _kb + (size_t)(b * LV_ + _s0 + rk[_i]) * E2_ + h * D_ + ckc; \
            uint32_t _o = 2u * (rk[_i] * PADC + ckc); \
            cpa16(_sb + _o, _row); \
            cpa16(_sb + TILE64B + _o, _row + E_); \
        } \
        asm volatile("cp.async.commit_group;" ::: "memory"); \
    } while (0)

    AKV(0);
    AKV(1);

    const int lr = lane & 15;
    const int lh = (lane >> 4) * 8;
    const int er = lane >> 2;
    const int ec = (lane & 3) * 2;
    const int tg  = lane >> 3;
    const int tlr = lane & 7;
    const int tko = (tg & 1) * 8;
    const int tno = (tg >> 1) * 8;

    const int row0 = m0 + mw * 16 + er;
    const int row1 = row0 + 8;

    float acc_c[8][4];
    #pragma unroll
    for (int j = 0; j < 8; j++)
        #pragma unroll
        for (int q = 0; q < 4; q++) acc_c[j][q] = 0.f;

    uint32_t qf[4][4];
    float rs0 = 0.f, rs1 = 0.f;

    for (int nt = 0; nt < 16; nt++) {
        asm volatile("cp.async.wait_group 1;" ::: "memory");
        __syncthreads();
        if (nt + 2 < 16) AKV(nt + 2);
        else asm volatile("cp.async.commit_group;" ::: "memory");

        if (nt == 0 || nt == 8) {
            uint32_t qb = base + QOFF + (nt == 8 ? TILE64B : 0);
            #pragma unroll
            for (int kf = 0; kf < 4; kf++)
                ldm_x4(qf[kf][0], qf[kf][1], qf[kf][2], qf[kf][3],
                       qb + 2u * ((mw * 16 + lr) * PADC + kf * 16 + lh));
        }

        const uint32_t kb = base + (nt % 3) * STGF;
        const uint32_t vb = kb + TILE64B;

        float acc_s[8][4];
        #pragma unroll
        for (int j = 0; j < 8; j++)
            #pragma unroll
            for (int q = 0; q < 4; q++) acc_s[j][q] = 0.f;

        #pragma unroll
        for (int kf = 0; kf < 4; kf++) {
            #pragma unroll
            for (int g = 0; g < 4; g++) {
                uint32_t br[4];
                ldm_x4(br[0], br[1], br[2], br[3],
                       kb + 2u * ((nh * 64 + g * 16 + lr) * PADC + kf * 16 + lh));
                mma_hf(acc_s[2 * g],     qf[kf], br[0], br[2]);
                mma_hf(acc_s[2 * g + 1], qf[kf], br[1], br[3]);
            }
        }

        const int nbase = nt * 128 + nh * 64;
        uint32_t ph[8][2];
        #pragma unroll
        for (int j = 0; j < 8; j++) {
            int n = nbase + j * 8 + ec;
            float2 mk0 = *(const float2*)(mask + (size_t)row0 * LS_ + n);
            float2 mk1 = *(const float2*)(mask + (size_t)row1 * LS_ + n);
            float e0 = __expf(fminf(acc_s[j][0] * 0.125f + mk0.x, 11.f));
            float e1 = __expf(fminf(acc_s[j][1] * 0.125f + mk0.y, 11.f));
            float e2 = __expf(fminf(acc_s[j][2] * 0.125f + mk1.x, 11.f));
            float e3 = __expf(fminf(acc_s[j][3] * 0.125f + mk1.y, 11.f));
            __half2 u01 = __floats2half2_rn(e0, e1);
            __half2 u23 = __floats2half2_rn(e2, e3);
            ph[j][0] = *(uint32_t*)&u01;
            ph[j][1] = *(uint32_t*)&u23;
            *(__half2*)(Eo + ((size_t)z * LO_ + row0) * LS_ + n) = u01;
            *(__half2*)(Eo + ((size_t)z * LO_ + row1) * LS_ + n) = u23;
            rs0 += e0 + e1;
            rs1 += e2 + e3;
        }

        #pragma unroll
        for (int kt = 0; kt < 4; kt++) {
            uint32_t pa[4] = {ph[2 * kt][0], ph[2 * kt][1],
                              ph[2 * kt + 1][0], ph[2 * kt + 1][1]};
            #pragma unroll
            for (int g = 0; g < 4; g++) {
                uint32_t rb[4];
                ldm_x4_t(rb[0], rb[1], rb[2], rb[3],
                         vb + 2u * ((nh * 64 + kt * 16 + tko + tlr) * PADC + g * 16 + tno));
                mma_hf(acc_c[2 * g],     pa, rb[0], rb[1]);
                mma_hf(acc_c[2 * g + 1], pa, rb[2], rb[3]);
            }
        }
    }
    #undef AKV

    rs0 += __shfl_xor_sync(~0u, rs0, 1);
    rs0 += __shfl_xor_sync(~0u, rs0, 2);
    rs1 += __shfl_xor_sync(~0u, rs1, 1);
    rs1 += __shfl_xor_sync(~0u, rs1, 2);

    __syncthreads();

    float* srs = (float*)smx;
    if ((lane & 3) == 0) {
        srs[(warp * 8 + er) * 2 + 0] = rs0;
        srs[(warp * 8 + er) * 2 + 1] = rs1;
    }
    if (nh == 1) {
        float* pane = (float*)(smx + 1024) + mw * 1024;
        #pragma unroll
        for (int j = 0; j < 8; j++)
            #pragma unroll
            for (int q = 0; q < 4; q++)
                pane[(j * 4 + q) * 32 + lane] = acc_c[j][q];
    }
    __syncthreads();

    if (nh == 0) {
        float pr0 = srs[((warp + 8) * 8 + er) * 2 + 0];
        float pr1 = srs[((warp + 8) * 8 + er) * 2 + 1];
        float inv0 = 1.f / (rs0 + pr0);
        float inv1 = 1.f / (rs1 + pr1);
        if ((lane & 3) == 0) {
            Inv[(size_t)z * LO_ + row0] = inv0;
            Inv[(size_t)z * LO_ + row1] = inv1;
        }
        const float* pane = (const float*)(smx + 1024) + mw * 1024;
        #pragma unroll
        for (int j = 0; j < 8; j++)
            #pragma unroll
            for (int q = 0; q < 4; q++)
                acc_c[j][q] += pane[(j * 4 + q) * 32 + lane];

        #pragma unroll
        for (int j = 0; j < 8; j++) {
            int nl = j * 8 + ec;
            __half* d0 = Cs + (size_t)(b * LO_ + row0) * RS2 + h * D_ + nl;
            __half* d1 = Cs + (size_t)(b * LO_ + row1) * RS2 + h * D_ + nl;
            __half h0, l0, h1, l1;
            fsplit_hf(acc_c[j][0] * inv0, h0, l0);
            fsplit_hf(acc_c[j][1] * inv0, h1, l1);
            *(__half2*)(d0)      = __half2(h0, h1);
            *(__half2*)(d0 + E_) = __half2(l0, l1);
            fsplit_hf(acc_c[j][2] * inv1, h0, l0);
            fsplit_hf(acc_c[j][3] * inv1, h1, l1);
            *(__half2*)(d1)      = __half2(h0, h1);
            *(__half2*)(d1 + E_) = __half2(l0, l1);
        }
    }
}

// ---------------------------------------------------------------------------
// Head-average: pure stream.
// ---------------------------------------------------------------------------
__global__ __launch_bounds__(512) void avg_kernel(
    const __half* __restrict__ E, const float* __restrict__ Inv,
    float* __restrict__ avg_out)
{
    __shared__ float sinv[H_];
    const int bt = blockIdx.x;
    const int b = bt / LO_, t = bt % LO_;
    const int tid = threadIdx.x;

    if (tid < H_) sinv[tid] = Inv[(size_t)(b * H_ + tid) * LO_ + t] * (1.f / H_);
    __syncthreads();

    float a0 = 0.f, a1 = 0.f, a2 = 0.f, a3 = 0.f;
    #pragma unroll
    for (int h = 0; h < H_; h++) {
        const __half2* Er = (const __half2*)(E + ((size_t)(b * H_ + h) * LO_ + t) * LS_);
        float sc = sinv[h];
        float2 u = __half22float2(Er[tid]);
        float2 w = __half22float2(Er[tid + 512]);
        a0 += u.x * sc; a1 += u.y * sc;
        a2 += w.x * sc; a3 += w.y * sc;
    }
    float2* A2 = (float2*)(avg_out + (size_t)bt * LS_);
    A2[tid]       = make_float2(a0, a1);
    A2[tid + 512] = make_float2(a2, a3);
}

// ---------------------------------------------------------------------------
// Launch (fork avg_kernel onto side stream, join before return)
// ---------------------------------------------------------------------------
extern "C" void kernel_launch(void* const* d_in, const int* in_sizes, int n_in,
                              void* d_out, int out_size)
{
    (void)in_sizes; (void)n_in; (void)out_size;

    const float* V    = (const float*)d_in[0];
    const float* L    = (const float*)d_in[1];
    const float* O    = (const float*)d_in[2];
    const float* mask = (const float*)d_in[3];
    const float* w1   = (const float*)d_in[4];
    const float* b1   = (const float*)d_in[5];
    const float* w2   = (const float*)d_in[6];
    const float* b2   = (const float*)d_in[7];
    const float* ow   = (const float*)d_in[8];
    const float* ob   = (const float*)d_in[9];

    float* out = (float*)d_out;
    float* avg = out + (size_t)B_ * LO_ * E_;

    __half *Oh, *Vh, *Lh, *w1h, *w2h, *qq, *kv1, *kv2, *Eh, *ctxh, *owh;
    float* Inv;
    cudaGetSymbolAddress((void**)&Oh,   g_Oh);
    cudaGetSymbolAddress((void**)&Vh,   g_Vh);
    cudaGetSymbolAddress((void**)&Lh,   g_Lh);
    cudaGetSymbolAddress((void**)&w1h,  g_w1h);
    cudaGetSymbolAddress((void**)&w2h,  g_w2h);
    cudaGetSymbolAddress((void**)&ctxh, g_ctxh);
    cudaGetSymbolAddress((void**)&owh,  g_owh);
    cudaGetSymbolAddress((void**)&qq,   g_qq);
    cudaGetSymbolAddress((void**)&kv1,  g_kv1);
    cudaGetSymbolAddress((void**)&kv2,  g_kv2);
    cudaGetSymbolAddress((void**)&Eh,   g_Eh);
    cudaGetSymbolAddress((void**)&Inv,  g_inv);

    cudaFuncSetAttribute(proj_qkv,   cudaFuncAttributeMaxDynamicSharedMemorySize, SMEM_PROJ);
    cudaFuncSetAttribute(proj_out,   cudaFuncAttributeMaxDynamicSharedMemorySize, SMEM_PROJ);
    cudaFuncSetAttribute(attn_fused, cudaFuncAttributeMaxDynamicSharedMemorySize, SMEM_ATTN);

    // Side stream + fork/join events (host objects; created at capture time,
    // no device allocation).
    cudaStream_t s2;
    cudaStreamCreateWithFlags(&s2, cudaStreamNonBlocking);
    cudaEvent_t evFork, evJoin;
    cudaEventCreateWithFlags(&evFork, cudaEventDisableTiming);
    cudaEventCreateWithFlags(&evJoin, cudaEventDisableTiming);

    // 1) Fused splits
    split_all<<<(ROW * (E_ / 4)) / 256, 256>>>(V, L, O, w1, w2, ow,
                                               Vh, Lh, Oh, w1h, w2h, owh);

    // 2) q/k/v projections
    proj_qkv<<<1920, 256, SMEM_PROJ>>>(Oh, Vh, Lh, w1h, w2h, b1, b2, qq, kv1, kv2);

    // 3) Fused attention
    dim3 gA(LO_ / 128, Z_);    // 4 x 96
    attn_fused<<<gA, 512, SMEM_ATTN>>>(qq, kv1, kv2, mask, Eh, Inv, ctxh);

    // Fork: avg (DRAM-bound) on s2, proj_out (tensor-bound) on main stream.
    cudaEventRecord(evFork, 0);
    cudaStreamWaitEvent(s2, evFork, 0);

    // 4) Head-average (side stream)
    avg_kernel<<<B_ * LO_, 512, 0, s2>>>(Eh, Inv, avg);

    // 5) Output projection (main stream)
    dim3 gO(E_ / 128, (B_ * LO_) / 128);
    proj_out<<<gO, 256, SMEM_PROJ>>>(ctxh, owh, ob, out);

    // Join
    cudaEventRecord(evJoin, s2);
    cudaStreamWaitEvent(0, evJoin, 0);
}